// round 2
// baseline (speedup 1.0000x reference)
#include <cuda_runtime.h>
#include <cstdint>

// ---------------------------------------------------------------------------
// Problem constants (shapes fixed by the reference): C=12, L=32, D=32, NOUT=2.
// A (alleles) and R (reads) derived from in_sizes at launch.
// NOTE: the count arrays are int32 on device (JAX default x64-disabled
// downcasts the reference's int64 arrays).
// ---------------------------------------------------------------------------

#define MAXA 16384
__device__ int g_offs0[MAXA];
__device__ int g_offs1[MAXA];

// Exclusive-scan of the two int32 count arrays (A <= MAXA), single block.
__global__ void rc_scan_kernel(const int* __restrict__ c0,
                               const int* __restrict__ c1, int A) {
    __shared__ int s0[1024], s1[1024];
    int t = threadIdx.x;
    int per = (A + 1023) >> 10;
    int base = t * per;
    int l0 = 0, l1 = 0;
    for (int i = 0; i < per; i++) {
        int idx = base + i;
        if (idx < A) { l0 += c0[idx]; l1 += c1[idx]; }
    }
    s0[t] = l0; s1[t] = l1;
    __syncthreads();
    for (int off = 1; off < 1024; off <<= 1) {
        int a0 = (t >= off) ? s0[t - off] : 0;
        int a1 = (t >= off) ? s1[t - off] : 0;
        __syncthreads();
        s0[t] += a0; s1[t] += a1;
        __syncthreads();
    }
    int ex0 = (t > 0) ? s0[t - 1] : 0;
    int ex1 = (t > 0) ? s1[t - 1] : 0;
    for (int i = 0; i < per; i++) {
        int idx = base + i;
        if (idx < A) {
            g_offs0[idx] = ex0; g_offs1[idx] = ex1;
            ex0 += c0[idx]; ex1 += c1[idx];
        }
    }
}

// ---------------------------------------------------------------------------
// tf32 helpers
// ---------------------------------------------------------------------------
__device__ __forceinline__ uint32_t f2tf32(float f) {
    uint32_t u;
    asm("cvt.rna.tf32.f32 %0, %1;" : "=r"(u) : "f"(f));
    return u;
}

__device__ __forceinline__ void mma_tf32(float c[4], const uint32_t a[4],
                                         uint32_t b0, uint32_t b1) {
    asm volatile(
        "mma.sync.aligned.m16n8k8.row.col.f32.tf32.tf32.f32 "
        "{%0,%1,%2,%3},{%4,%5,%6,%7},{%8,%9},{%0,%1,%2,%3};"
        : "+f"(c[0]), "+f"(c[1]), "+f"(c[2]), "+f"(c[3])
        : "r"(a[0]), "r"(a[1]), "r"(a[2]), "r"(a[3]), "r"(b0), "r"(b1));
}

// ---------------------------------------------------------------------------
// Main kernel: one block (256 threads = 8 warps) per allele.
//
// z[d, col] = relu( sum_c W[d,c] * T[c, col] + b[d] ),  col = (read,l) pairs
// y[a, d]   = sum over all cols of the allele, then / (depth * 32)
// out[a, n] = sum_d y_cat[a, d] * W2[n, d] + b2[n]
//
// MMA tiling (m16n8k8 tf32): M = d (2 tiles of 16), K = c (2 steps; c=12
// padded to 16, with c==12 carrying the bias via a synthetic ones-channel),
// N = 8 l-columns per chunk. Warps stride over chunks; relu + column-sum is
// done on the register C fragment immediately (no smem/TMEM round trip).
// ---------------------------------------------------------------------------
__global__ __launch_bounds__(256) void rc_main_kernel(
    const float* __restrict__ t0, const float* __restrict__ t1,
    const float* __restrict__ W0, const float* __restrict__ b0,
    const float* __restrict__ W1, const float* __restrict__ b1,
    const float* __restrict__ W2, const float* __restrict__ b2,
    const int* __restrict__ cnt0, const int* __restrict__ cnt1,
    const float* __restrict__ dm0, const float* __restrict__ dm1,
    float* __restrict__ out)
{
    const int a   = blockIdx.x;
    const int tid = threadIdx.x;
    const int wid = tid >> 5, lane = tid & 31;
    const int qp  = lane >> 2;   // groupID: C-frag row / B-frag column (l)
    const int rp  = lane & 3;    // threadID-in-group: A/B k index, C column pair

    __shared__ float sY[2][32][8];
    __shared__ float sPool[64];

    const uint32_t one_tf = f2tf32(1.0f);

    #pragma unroll 1
    for (int s = 0; s < 2; s++) {
        const float* T  = s ? t1 : t0;
        const float* W  = s ? W1 : W0;
        const float* Bv = s ? b1 : b0;
        const int off = s ? g_offs1[a] : g_offs0[a];
        const int cnt = s ? cnt1[a] : cnt0[a];

        // A fragments: af[m_tile][k_step][0..3]
        uint32_t af[2][2][4];
        #pragma unroll
        for (int m = 0; m < 2; m++) {
            int r0 = qp + 16 * m, r1 = r0 + 8;
            af[m][0][0] = f2tf32(W[r0 * 12 + rp]);
            af[m][0][1] = f2tf32(W[r1 * 12 + rp]);
            af[m][0][2] = f2tf32(W[r0 * 12 + rp + 4]);
            af[m][0][3] = f2tf32(W[r1 * 12 + rp + 4]);
            af[m][1][0] = f2tf32(W[r0 * 12 + rp + 8]);   // c = 8..11
            af[m][1][1] = f2tf32(W[r1 * 12 + rp + 8]);
            af[m][1][2] = (rp == 0) ? f2tf32(Bv[r0]) : 0u;  // c==12: bias
            af[m][1][3] = (rp == 0) ? f2tf32(Bv[r1]) : 0u;  // c==13..15: zero
        }
        const uint32_t bk1 = (rp == 0) ? one_tf : 0u;  // ones-channel (c==12)

        float acc[4] = {0.f, 0.f, 0.f, 0.f};
        const int nchunks = cnt << 2;   // 4 chunks of 8 l-columns per read
        for (int ci = wid; ci < nchunks; ci += 8) {
            const float* base =
                T + (size_t)(off + (ci >> 2)) * 384 + ((ci & 3) << 3) + qp;
            // B fragment rows are c; stride between c values is L=32 floats
            uint32_t bb0 = f2tf32(base[rp * 32]);         // c = rp
            uint32_t bb1 = f2tf32(base[rp * 32 + 128]);   // c = rp + 4
            uint32_t bb2 = f2tf32(base[rp * 32 + 256]);   // c = rp + 8
            #pragma unroll
            for (int m = 0; m < 2; m++) {
                float c[4] = {0.f, 0.f, 0.f, 0.f};
                mma_tf32(c, af[m][0], bb0, bb1);
                mma_tf32(c, af[m][1], bb2, bk1);
                acc[2 * m]     += fmaxf(c[0], 0.f) + fmaxf(c[1], 0.f);
                acc[2 * m + 1] += fmaxf(c[2], 0.f) + fmaxf(c[3], 0.f);
            }
        }
        // reduce the C-fragment column groups (4 threads hold the 8 columns)
        #pragma unroll
        for (int i = 0; i < 4; i++) {
            acc[i] += __shfl_xor_sync(0xffffffffu, acc[i], 1);
            acc[i] += __shfl_xor_sync(0xffffffffu, acc[i], 2);
        }
        if (rp == 0) {
            sY[s][qp][wid]      = acc[0];
            sY[s][qp + 8][wid]  = acc[1];
            sY[s][qp + 16][wid] = acc[2];
            sY[s][qp + 24][wid] = acc[3];
        }
    }
    __syncthreads();

    if (tid < 64) {
        int s = tid >> 5, d = tid & 31;
        float v = 0.f;
        #pragma unroll
        for (int w = 0; w < 8; w++) v += sY[s][d][w];
        float dep = s ? dm1[a] : dm0[a];
        sPool[tid] = v / (dep * 32.0f);   // depth-normalize + mean over L
    }
    __syncthreads();

    if (tid < 2) {
        float v = b2[tid];
        #pragma unroll
        for (int j = 0; j < 64; j++) v += sPool[j] * W2[tid * 64 + j];
        out[a * 2 + tid] = v;
    }
}

// ---------------------------------------------------------------------------
extern "C" void kernel_launch(void* const* d_in, const int* in_sizes, int n_in,
                              void* d_out, int out_size) {
    const float* t0  = (const float*)d_in[0];
    const float* t1  = (const float*)d_in[1];
    const float* W0  = (const float*)d_in[2];
    const float* b0  = (const float*)d_in[3];
    const float* W1  = (const float*)d_in[4];
    const float* b1  = (const float*)d_in[5];
    const float* W2  = (const float*)d_in[6];
    const float* b2  = (const float*)d_in[7];
    const int*   c0  = (const int*)d_in[8];
    const int*   c1  = (const int*)d_in[9];
    // d_in[10]: numAllelesPerSite (unused by the reference output)
    const float* dm0 = (const float*)d_in[11];
    const float* dm1 = (const float*)d_in[12];
    float* out = (float*)d_out;

    int A = in_sizes[8];   // alleles

    rc_scan_kernel<<<1, 1024>>>(c0, c1, A);
    rc_main_kernel<<<A, 256>>>(t0, t1, W0, b0, W1, b1, W2, b2,
                               c0, c1, dm0, dm1, out);
}

// round 3
// speedup vs baseline: 1.3437x; 1.3437x over previous
#include <cuda_runtime.h>
#include <cstdint>

// ---------------------------------------------------------------------------
// C=12, L=32, D=32, NOUT=2. Counts are int32 on device (JAX x64-off downcast).
// ---------------------------------------------------------------------------

#define MAXA 16384
#define APB 4   // alleles per block
__device__ int g_offs0[MAXA];
__device__ int g_offs1[MAXA];

__global__ void rc_scan_kernel(const int* __restrict__ c0,
                               const int* __restrict__ c1, int A) {
    __shared__ int s0[1024], s1[1024];
    int t = threadIdx.x;
    int per = (A + 1023) >> 10;
    int base = t * per;
    int l0 = 0, l1 = 0;
    for (int i = 0; i < per; i++) {
        int idx = base + i;
        if (idx < A) { l0 += c0[idx]; l1 += c1[idx]; }
    }
    s0[t] = l0; s1[t] = l1;
    __syncthreads();
    for (int off = 1; off < 1024; off <<= 1) {
        int a0 = (t >= off) ? s0[t - off] : 0;
        int a1 = (t >= off) ? s1[t - off] : 0;
        __syncthreads();
        s0[t] += a0; s1[t] += a1;
        __syncthreads();
    }
    int ex0 = (t > 0) ? s0[t - 1] : 0;
    int ex1 = (t > 0) ? s1[t - 1] : 0;
    for (int i = 0; i < per; i++) {
        int idx = base + i;
        if (idx < A) {
            g_offs0[idx] = ex0; g_offs1[idx] = ex1;
            ex0 += c0[idx]; ex1 += c1[idx];
        }
    }
}

__device__ __forceinline__ uint32_t f2tf32(float f) {
    uint32_t u;
    asm("cvt.rna.tf32.f32 %0, %1;" : "=r"(u) : "f"(f));
    return u;
}

__device__ __forceinline__ void mma_tf32(float c[4], const uint32_t a[4],
                                         uint32_t b0, uint32_t b1) {
    asm volatile(
        "mma.sync.aligned.m16n8k8.row.col.f32.tf32.tf32.f32 "
        "{%0,%1,%2,%3},{%4,%5,%6,%7},{%8,%9},{%0,%1,%2,%3};"
        : "+f"(c[0]), "+f"(c[1]), "+f"(c[2]), "+f"(c[3])
        : "r"(a[0]), "r"(a[1]), "r"(a[2]), "r"(a[3]), "r"(b0), "r"(b1));
}

// ---------------------------------------------------------------------------
// One block = APB alleles. Warps 0-3 process source 0, warps 4-7 source 1.
// Warp wq (0-3 within its source) handles l-columns [8wq, 8wq+8) of EVERY
// read of the allele -> inner loop is a pure pointer-bump (+384 floats/read),
// unrolled x2 for 6 LDGs in flight. W/bias MMA A-fragments built once per
// block (identical across alleles).
// ---------------------------------------------------------------------------
__global__ __launch_bounds__(256) void rc_main_kernel(
    const float* __restrict__ t0, const float* __restrict__ t1,
    const float* __restrict__ W0, const float* __restrict__ b0,
    const float* __restrict__ W1, const float* __restrict__ b1,
    const float* __restrict__ W2, const float* __restrict__ b2,
    const int* __restrict__ cnt0, const int* __restrict__ cnt1,
    const float* __restrict__ dm0, const float* __restrict__ dm1,
    float* __restrict__ out, int nA)
{
    const int tid  = threadIdx.x;
    const int wid  = tid >> 5, lane = tid & 31;
    const int qp   = lane >> 2;      // C-frag row group / B-frag column (l)
    const int rp   = lane & 3;       // k index within fragment
    const int sgrp = wid >> 2;       // source (0/1)
    const int wq   = wid & 3;        // warp within source group

    __shared__ float sY[APB][2][32][4];
    __shared__ float sPool[APB][64];

    const float* T   = sgrp ? t1 : t0;
    const float* W   = sgrp ? W1 : W0;
    const float* Bv  = sgrp ? b1 : b0;
    const int* cnts  = sgrp ? cnt1 : cnt0;
    const int* offs  = sgrp ? g_offs1 : g_offs0;

    // A fragments: af[m_tile][k_step][0..3]  (built once per block)
    uint32_t af[2][2][4];
    #pragma unroll
    for (int m = 0; m < 2; m++) {
        int r0 = qp + 16 * m, r1 = r0 + 8;
        af[m][0][0] = f2tf32(W[r0 * 12 + rp]);
        af[m][0][1] = f2tf32(W[r1 * 12 + rp]);
        af[m][0][2] = f2tf32(W[r0 * 12 + rp + 4]);
        af[m][0][3] = f2tf32(W[r1 * 12 + rp + 4]);
        af[m][1][0] = f2tf32(W[r0 * 12 + rp + 8]);      // c = 8..11
        af[m][1][1] = f2tf32(W[r1 * 12 + rp + 8]);
        af[m][1][2] = (rp == 0) ? f2tf32(Bv[r0]) : 0u;  // c==12: bias
        af[m][1][3] = (rp == 0) ? f2tf32(Bv[r1]) : 0u;  // c==13..15: zero
    }
    const uint32_t bk1 = (rp == 0) ? f2tf32(1.0f) : 0u; // ones-channel

    const int aBase = blockIdx.x * APB;

    #pragma unroll
    for (int ai = 0; ai < APB; ai++) {
        const int a = aBase + ai;
        float acc[4] = {0.f, 0.f, 0.f, 0.f};
        if (a < nA) {
            const int cnt = cnts[a];
            // element for this lane: l = 8*wq + qp, c = rp + {0,4,8}
            const float* p = T + (size_t)offs[a] * 384 + wq * 8 + qp + rp * 32;
            int j = 0;
            for (; j + 1 < cnt; j += 2) {           // 2 reads / iter: 6 LDGs
                float x0 = p[0],   x1 = p[128], x2 = p[256];
                float y0 = p[384], y1 = p[512], y2 = p[640];
                p += 768;
                uint32_t bx0 = f2tf32(x0), bx1 = f2tf32(x1), bx2 = f2tf32(x2);
                uint32_t by0 = f2tf32(y0), by1 = f2tf32(y1), by2 = f2tf32(y2);
                #pragma unroll
                for (int m = 0; m < 2; m++) {
                    float c[4] = {0.f, 0.f, 0.f, 0.f};
                    mma_tf32(c, af[m][0], bx0, bx1);
                    mma_tf32(c, af[m][1], bx2, bk1);
                    float d[4] = {0.f, 0.f, 0.f, 0.f};
                    mma_tf32(d, af[m][0], by0, by1);
                    mma_tf32(d, af[m][1], by2, bk1);
                    acc[2 * m]     += fmaxf(c[0], 0.f) + fmaxf(c[1], 0.f)
                                    + fmaxf(d[0], 0.f) + fmaxf(d[1], 0.f);
                    acc[2 * m + 1] += fmaxf(c[2], 0.f) + fmaxf(c[3], 0.f)
                                    + fmaxf(d[2], 0.f) + fmaxf(d[3], 0.f);
                }
            }
            if (j < cnt) {                           // odd tail read
                uint32_t bx0 = f2tf32(p[0]), bx1 = f2tf32(p[128]),
                         bx2 = f2tf32(p[256]);
                #pragma unroll
                for (int m = 0; m < 2; m++) {
                    float c[4] = {0.f, 0.f, 0.f, 0.f};
                    mma_tf32(c, af[m][0], bx0, bx1);
                    mma_tf32(c, af[m][1], bx2, bk1);
                    acc[2 * m]     += fmaxf(c[0], 0.f) + fmaxf(c[1], 0.f);
                    acc[2 * m + 1] += fmaxf(c[2], 0.f) + fmaxf(c[3], 0.f);
                }
            }
            #pragma unroll
            for (int i = 0; i < 4; i++) {            // fold 8 cols -> 1 (rp==0)
                acc[i] += __shfl_xor_sync(0xffffffffu, acc[i], 1);
                acc[i] += __shfl_xor_sync(0xffffffffu, acc[i], 2);
            }
        }
        if (rp == 0) {
            sY[ai][sgrp][qp][wq]      = acc[0];
            sY[ai][sgrp][qp + 8][wq]  = acc[1];
            sY[ai][sgrp][qp + 16][wq] = acc[2];
            sY[ai][sgrp][qp + 24][wq] = acc[3];
        }
    }
    __syncthreads();

    // pooled: 256 threads cover APB*2*32 entries exactly
    {
        const int ai = tid >> 6, s = (tid >> 5) & 1, d = tid & 31;
        const int a = aBase + ai;
        if (a < nA) {
            float v = sY[ai][s][d][0] + sY[ai][s][d][1]
                    + sY[ai][s][d][2] + sY[ai][s][d][3];
            float dep = s ? dm1[a] : dm0[a];
            sPool[ai][s * 32 + d] = v / (dep * 32.0f);
        }
    }
    __syncthreads();

    if (tid < 2 * APB) {
        const int ai = tid >> 1, n = tid & 1;
        const int a = aBase + ai;
        if (a < nA) {
            float v = b2[n];
            #pragma unroll
            for (int jj = 0; jj < 64; jj++) v += sPool[ai][jj] * W2[n * 64 + jj];
            out[a * 2 + n] = v;
        }
    }
}

// ---------------------------------------------------------------------------
extern "C" void kernel_launch(void* const* d_in, const int* in_sizes, int n_in,
                              void* d_out, int out_size) {
    const float* t0  = (const float*)d_in[0];
    const float* t1  = (const float*)d_in[1];
    const float* W0  = (const float*)d_in[2];
    const float* b0  = (const float*)d_in[3];
    const float* W1  = (const float*)d_in[4];
    const float* b1  = (const float*)d_in[5];
    const float* W2  = (const float*)d_in[6];
    const float* b2  = (const float*)d_in[7];
    const int*   c0  = (const int*)d_in[8];
    const int*   c1  = (const int*)d_in[9];
    const float* dm0 = (const float*)d_in[11];
    const float* dm1 = (const float*)d_in[12];
    float* out = (float*)d_out;

    int A = in_sizes[8];

    rc_scan_kernel<<<1, 1024>>>(c0, c1, A);
    rc_main_kernel<<<(A + APB - 1) / APB, 256>>>(t0, t1, W0, b0, W1, b1,
                                                 W2, b2, c0, c1, dm0, dm1,
                                                 out, A);
}

// round 4
// speedup vs baseline: 1.6262x; 1.2103x over previous
#include <cuda_runtime.h>
#include <cstdint>

// ---------------------------------------------------------------------------
// C=12, L=32, D=32, NOUT=2. Counts are int32 on device (JAX x64-off).
// Two-phase: dense per-read relu-sums -> scratch, then ragged segment reduce.
// ---------------------------------------------------------------------------

#define MAXR 131072
__device__ float g_rsum0[MAXR * 32];   // per-read d-sums, source 0
__device__ float g_rsum1[MAXR * 32];   // per-read d-sums, source 1

__device__ __forceinline__ uint32_t f2tf32(float f) {
    uint32_t u;
    asm("cvt.rna.tf32.f32 %0, %1;" : "=r"(u) : "f"(f));
    return u;
}

__device__ __forceinline__ void mma_tf32(float c[4], const uint32_t a[4],
                                         uint32_t b0, uint32_t b1) {
    asm volatile(
        "mma.sync.aligned.m16n8k8.row.col.f32.tf32.tf32.f32 "
        "{%0,%1,%2,%3},{%4,%5,%6,%7},{%8,%9},{%0,%1,%2,%3};"
        : "+f"(c[0]), "+f"(c[1]), "+f"(c[2]), "+f"(c[3])
        : "r"(a[0]), "r"(a[1]), "r"(a[2]), "r"(a[3]), "r"(b0), "r"(b1));
}

// ---------------------------------------------------------------------------
// Phase 1: dense grid-stride over reads. blockIdx.y selects the source.
// Warp-private smem staging, double-buffered:
//   LDG.128 x3 (512B contiguous each) -> STS.128 x3 (XOR-swizzled) ->
//   LDS.128 x3 -> 16 tf32 MMAs -> relu+col-sum -> 8 SHFL fold -> STG x4.
// Chunk j uses l-columns {4*qp + j}: the float4 loaded per lane provides the
// B fragment component for all 4 chunks directly (no per-chunk LDS).
// ---------------------------------------------------------------------------
__global__ __launch_bounds__(256) void rc_phase1(
    const float* __restrict__ t0, const float* __restrict__ t1,
    const float* __restrict__ W0, const float* __restrict__ b0,
    const float* __restrict__ W1, const float* __restrict__ b1, int R)
{
    const int s = blockIdx.y;
    const float* T  = s ? t1 : t0;
    const float* W  = s ? W1 : W0;
    const float* Bv = s ? b1 : b0;
    float* Out      = s ? g_rsum1 : g_rsum0;

    const int tid  = threadIdx.x;
    const int wid  = tid >> 5, lane = tid & 31;
    const int qp   = lane >> 2, rp = lane & 3;   // MMA fragment coords
    const int g    = lane >> 3, h = lane & 7;    // staging coords

    __shared__ float4 buf[8][2][96];             // per-warp double buffer

    // A fragments af[m_tile][k_step][0..3] (W rows = d, cols = c; bias as c=12)
    uint32_t af[2][2][4];
    #pragma unroll
    for (int m = 0; m < 2; m++) {
        int r0 = qp + 16 * m, r1 = r0 + 8;
        af[m][0][0] = f2tf32(W[r0 * 12 + rp]);
        af[m][0][1] = f2tf32(W[r1 * 12 + rp]);
        af[m][0][2] = f2tf32(W[r0 * 12 + rp + 4]);
        af[m][0][3] = f2tf32(W[r1 * 12 + rp + 4]);
        af[m][1][0] = f2tf32(W[r0 * 12 + rp + 8]);
        af[m][1][1] = f2tf32(W[r1 * 12 + rp + 8]);
        af[m][1][2] = (rp == 0) ? f2tf32(Bv[r0]) : 0u;
        af[m][1][3] = (rp == 0) ? f2tf32(Bv[r1]) : 0u;
    }
    const uint32_t bk1 = (rp == 0) ? f2tf32(1.0f) : 0u;

    // swizzled float4 slot indices (row-major 12 rows x 8 float4 slots)
    const int sw_st = h ^ (2 * g);       // STS: logical slot h, rows g+4k
    const int sts0 = g * 8 + sw_st, sts1 = (g + 4) * 8 + sw_st,
              sts2 = (g + 8) * 8 + sw_st;
    const int sw_ld = qp ^ (2 * rp);     // LDS: logical slot qp, rows rp+4k
    const int lds0 = rp * 8 + sw_ld, lds1 = (rp + 4) * 8 + sw_ld,
              lds2 = (rp + 8) * 8 + sw_ld;

    const int WT = gridDim.x * 8;        // total warps
    int r = blockIdx.x * 8 + wid;

    float4 A0, A1, A2;
    if (r < R) {
        const float4* p = (const float4*)T + (size_t)r * 96;
        A0 = p[g * 8 + h]; A1 = p[(g + 4) * 8 + h]; A2 = p[(g + 8) * 8 + h];
    }
    int pp = 0;
    while (r < R) {
        float4* B = buf[wid][pp];
        B[sts0] = A0; B[sts1] = A1; B[sts2] = A2;
        const int rn = r + WT;
        if (rn < R) {                    // prefetch next read during consume
            const float4* p = (const float4*)T + (size_t)rn * 96;
            A0 = p[g * 8 + h]; A1 = p[(g + 4) * 8 + h]; A2 = p[(g + 8) * 8 + h];
        }
        __syncwarp();

        float4 x0 = B[lds0], x1 = B[lds1], x2 = B[lds2];
        uint32_t u0[4] = {f2tf32(x0.x), f2tf32(x0.y), f2tf32(x0.z), f2tf32(x0.w)};
        uint32_t u1[4] = {f2tf32(x1.x), f2tf32(x1.y), f2tf32(x1.z), f2tf32(x1.w)};
        uint32_t u2[4] = {f2tf32(x2.x), f2tf32(x2.y), f2tf32(x2.z), f2tf32(x2.w)};

        float acc[4] = {0.f, 0.f, 0.f, 0.f};
        #pragma unroll
        for (int j = 0; j < 4; j++) {
            #pragma unroll
            for (int m = 0; m < 2; m++) {
                float c[4] = {0.f, 0.f, 0.f, 0.f};
                mma_tf32(c, af[m][0], u0[j], u1[j]);
                mma_tf32(c, af[m][1], u2[j], bk1);
                acc[2 * m]     += fmaxf(c[0], 0.f) + fmaxf(c[1], 0.f);
                acc[2 * m + 1] += fmaxf(c[2], 0.f) + fmaxf(c[3], 0.f);
            }
        }
        #pragma unroll
        for (int i = 0; i < 4; i++) {    // fold column groups over rp
            acc[i] += __shfl_xor_sync(0xffffffffu, acc[i], 1);
            acc[i] += __shfl_xor_sync(0xffffffffu, acc[i], 2);
        }
        if (rp == 0) {                   // d = 8*i + qp
            float* o = Out + (size_t)r * 32 + qp;
            o[0] = acc[0]; o[8] = acc[1]; o[16] = acc[2]; o[24] = acc[3];
        }
        r = rn; pp ^= 1;
        __syncwarp();                    // protect buffer reuse next iter+1
    }
}

// ---------------------------------------------------------------------------
// Phase 2: one warp per allele; block computes its own offsets (no scan
// kernel). Coalesced 128B loads of per-read sums; normalize; 64->2 head.
// ---------------------------------------------------------------------------
__global__ __launch_bounds__(256) void rc_phase2(
    const int* __restrict__ cnt0, const int* __restrict__ cnt1,
    const float* __restrict__ dm0, const float* __restrict__ dm1,
    const float* __restrict__ W2, const float* __restrict__ b2,
    float* __restrict__ out, int A)
{
    const int tid = threadIdx.x, wid = tid >> 5, lane = tid & 31;
    const int aBase = blockIdx.x * 8;

    __shared__ int sred[2][8];
    __shared__ int sOff[2];

    int a0 = 0, a1 = 0;
    for (int i = tid; i < aBase; i += 256) { a0 += cnt0[i]; a1 += cnt1[i]; }
    #pragma unroll
    for (int o = 16; o; o >>= 1) {
        a0 += __shfl_xor_sync(0xffffffffu, a0, o);
        a1 += __shfl_xor_sync(0xffffffffu, a1, o);
    }
    if (lane == 0) { sred[0][wid] = a0; sred[1][wid] = a1; }
    __syncthreads();
    if (tid == 0) {
        int t0 = 0, t1 = 0;
        #pragma unroll
        for (int i = 0; i < 8; i++) { t0 += sred[0][i]; t1 += sred[1][i]; }
        sOff[0] = t0; sOff[1] = t1;
    }
    __syncthreads();

    const int a = aBase + wid;
    if (a >= A) return;

    int off0 = sOff[0], off1 = sOff[1];
    for (int i = 0; i < wid; i++) { off0 += cnt0[aBase + i]; off1 += cnt1[aBase + i]; }
    const int c0 = cnt0[a], c1 = cnt1[a];

    const float* p0 = g_rsum0 + (size_t)off0 * 32 + lane;
    float s0 = 0.f;
    #pragma unroll 4
    for (int i = 0; i < c0; i++) s0 += p0[i * 32];
    const float* p1 = g_rsum1 + (size_t)off1 * 32 + lane;
    float s1 = 0.f;
    #pragma unroll 4
    for (int i = 0; i < c1; i++) s1 += p1[i * 32];

    s0 /= (dm0[a] * 32.f);
    s1 /= (dm1[a] * 32.f);

    float q0 = s0 * W2[lane]      + s1 * W2[32 + lane];
    float q1 = s0 * W2[64 + lane] + s1 * W2[96 + lane];
    #pragma unroll
    for (int o = 16; o; o >>= 1) {
        q0 += __shfl_xor_sync(0xffffffffu, q0, o);
        q1 += __shfl_xor_sync(0xffffffffu, q1, o);
    }
    if (lane == 0) { out[2 * a] = q0 + b2[0]; out[2 * a + 1] = q1 + b2[1]; }
}

// ---------------------------------------------------------------------------
extern "C" void kernel_launch(void* const* d_in, const int* in_sizes, int n_in,
                              void* d_out, int out_size) {
    const float* t0  = (const float*)d_in[0];
    const float* t1  = (const float*)d_in[1];
    const float* W0  = (const float*)d_in[2];
    const float* b0  = (const float*)d_in[3];
    const float* W1  = (const float*)d_in[4];
    const float* b1  = (const float*)d_in[5];
    const float* W2  = (const float*)d_in[6];
    const float* b2  = (const float*)d_in[7];
    const int*   c0  = (const int*)d_in[8];
    const int*   c1  = (const int*)d_in[9];
    const float* dm0 = (const float*)d_in[11];
    const float* dm1 = (const float*)d_in[12];
    float* out = (float*)d_out;

    const int A = in_sizes[8];
    const int R = in_sizes[0] / 384;   // reads per source (C*L = 384)

    dim3 grid1(1024, 2);
    rc_phase1<<<grid1, 256>>>(t0, t1, W0, b0, W1, b1, R);
    rc_phase2<<<(A + 7) / 8, 256>>>(c0, c1, dm0, dm1, W2, b2, out, A);
}